// round 16
// baseline (speedup 1.0000x reference)
#include <cuda_runtime.h>
#include <cuda_bf16.h>
#include <math.h>

#define BQ 16384
#define DIN 4000
#define HD 512
#define LD 256
#define EBM1 0.6487212707001282f  // exp(0.5)-1

__device__ float g_h[(size_t)BQ * HD];
__device__ __nv_bfloat16 g_hb[(size_t)BQ * HD];
__device__ __nv_bfloat16 g_w2b[(size_t)HD * DIN];
__device__ float g_q[(size_t)BQ * LD];
__device__ float g_zeta[(size_t)BQ * LD];
__device__ float g_zb[(size_t)BQ * LD];
__device__ float g_rowpos[BQ];
__device__ float g_rowneg[BQ];
__device__ float g_part[4096];
__device__ float g_ps[16 * HD];
__device__ float g_pss[16 * HD];
__device__ float g_scale[HD];
__device__ float g_shift[HD];

__device__ __forceinline__ float fsigmoid(float x) { return 1.0f / (1.0f + expf(-x)); }
__device__ __forceinline__ unsigned su32(const void* p) { return (unsigned)__cvta_generic_to_shared(p); }

#define LDSM4(a0,a1,a2,a3,addr) \
    asm volatile("ldmatrix.sync.aligned.m8n8.x4.shared.b16 {%0,%1,%2,%3},[%4];" \
                 : "=r"(a0),"=r"(a1),"=r"(a2),"=r"(a3) : "r"(addr))
#define LDSM4T(a0,a1,a2,a3,addr) \
    asm volatile("ldmatrix.sync.aligned.m8n8.x4.trans.shared.b16 {%0,%1,%2,%3},[%4];" \
                 : "=r"(a0),"=r"(a1),"=r"(a2),"=r"(a3) : "r"(addr))
#define MMA16816(c,a0,a1,a2,a3,b0,b1) \
    asm volatile("mma.sync.aligned.m16n8k16.row.col.f32.bf16.bf16.f32 " \
                 "{%0,%1,%2,%3},{%4,%5,%6,%7},{%8,%9},{%0,%1,%2,%3};" \
                 : "+f"((c)[0]),"+f"((c)[1]),"+f"((c)[2]),"+f"((c)[3]) \
                 : "r"(a0),"r"(a1),"r"(a2),"r"(a3),"r"(b0),"r"(b1))
#define MMATF32(c,a0,a1,a2,a3,b0,b1) \
    asm volatile("mma.sync.aligned.m16n8k8.row.col.f32.tf32.tf32.f32 " \
                 "{%0,%1,%2,%3},{%4,%5,%6,%7},{%8,%9},{%0,%1,%2,%3};" \
                 : "+f"((c)[0]),"+f"((c)[1]),"+f"((c)[2]),"+f"((c)[3]) \
                 : "r"(a0),"r"(a1),"r"(a2),"r"(a3),"r"(b0),"r"(b1))
#define CPA16(s,g)      asm volatile("cp.async.cg.shared.global [%0],[%1],16;" :: "r"(s),"l"(g))
#define CPA16Z(s,g,sz)  asm volatile("cp.async.cg.shared.global [%0],[%1],16,%2;" :: "r"(s),"l"(g),"r"(sz))
#define CPCOMMIT()      asm volatile("cp.async.commit_group;")
#define CPWAIT0()       asm volatile("cp.async.wait_group 0;")

__device__ __forceinline__ void tf32_split_u(float x, unsigned& hi, unsigned& lo) {
    asm("cvt.rna.tf32.f32 %0,%1;" : "=r"(hi) : "f"(x));
    float lf = x - __uint_as_float(hi);
    asm("cvt.rna.tf32.f32 %0,%1;" : "=r"(lo) : "f"(lf));
}

// ================= tf32x3 GEMM v2: 128x256 block, 64x64 warp tiles =================
#define V2_PA 20
#define V2_PB 260
#define V2_NSMA (128 * V2_PA)
#define V2_NSMB (16 * V2_PB)
#define V2_SMEM ((2 * (V2_NSMA + V2_NSMB)) * 4)

template <int MODE>
__global__ __launch_bounds__(256)
void gemm_v2(const float* __restrict__ A, int lda,
             const float* __restrict__ B, int ldb,
             const float* __restrict__ bias,
             float* __restrict__ C, int ldc, int K,
             const float* __restrict__ aux,
             float* __restrict__ o1, float* __restrict__ o2, float* __restrict__ o3)
{
    extern __shared__ __align__(16) float smv2[];
    float* Asm = smv2;
    float* Bsm = smv2 + 2 * V2_NSMA;

    const int tid = threadIdx.x;
    const int lane = tid & 31;
    const int w = tid >> 5;
    const int wm = w & 1;
    const int wn = w >> 1;
    const int m0 = blockIdx.y * 128;
    const int n0 = blockIdx.x * 256;
    const int gid = lane >> 2, q = lane & 3;

    const int arow0 = tid >> 2, ac0 = (tid & 3) * 4;
    const int arow1 = (tid + 256) >> 2, ac1 = ((tid + 256) & 3) * 4;

    auto load_stage = [&](int buf, int k0) {
        unsigned sa = su32(Asm + buf * V2_NSMA);
        CPA16(sa + (arow0 * V2_PA + ac0) * 4, A + (size_t)(m0 + arow0) * lda + k0 + ac0);
        CPA16(sa + (arow1 * V2_PA + ac1) * 4, A + (size_t)(m0 + arow1) * lda + k0 + ac1);
        unsigned sb2 = su32(Bsm + buf * V2_NSMB);
#pragma unroll
        for (int i = 0; i < 4; i++) {
            int cb = tid + i * 256;
            int brow = cb >> 6, bc = (cb & 63) * 4;
            CPA16(sb2 + (brow * V2_PB + bc) * 4, B + (size_t)(k0 + brow) * ldb + n0 + bc);
        }
        CPCOMMIT();
    };

    float c[4][8][4];
#pragma unroll
    for (int i = 0; i < 4; i++)
#pragma unroll
        for (int j = 0; j < 8; j++)
#pragma unroll
            for (int e = 0; e < 4; e++) c[i][j][e] = 0.f;

    const int NS = K / 16;
    load_stage(0, 0);
    for (int s = 0; s < NS; s++) {
        CPWAIT0();
        __syncthreads();
        if (s + 1 < NS) load_stage((s + 1) & 1, (s + 1) * 16);
        const float* As = Asm + (s & 1) * V2_NSMA;
        const float* Bs = Bsm + (s & 1) * V2_NSMB;
#pragma unroll
        for (int ks = 0; ks < 2; ks++) {
            const int kb = ks * 8;
            unsigned ah[4][4], al[4][4];
#pragma unroll
            for (int mt = 0; mt < 4; mt++) {
                const int mB = wm * 64 + mt * 16;
                float r0 = As[(mB + gid) * V2_PA + kb + q];
                float r1 = As[(mB + gid + 8) * V2_PA + kb + q];
                float r2 = As[(mB + gid) * V2_PA + kb + 4 + q];
                float r3 = As[(mB + gid + 8) * V2_PA + kb + 4 + q];
                tf32_split_u(r0, ah[mt][0], al[mt][0]);
                tf32_split_u(r1, ah[mt][1], al[mt][1]);
                tf32_split_u(r2, ah[mt][2], al[mt][2]);
                tf32_split_u(r3, ah[mt][3], al[mt][3]);
            }
#pragma unroll
            for (int nt = 0; nt < 8; nt++) {
                const int nB = wn * 64 + nt * 8;
                float b0 = Bs[(kb + q) * V2_PB + nB + gid];
                float b1 = Bs[(kb + 4 + q) * V2_PB + nB + gid];
                unsigned bh0, bl0, bh1, bl1;
                tf32_split_u(b0, bh0, bl0);
                tf32_split_u(b1, bh1, bl1);
#pragma unroll
                for (int mt = 0; mt < 4; mt++) {
                    MMATF32(c[mt][nt], ah[mt][0], ah[mt][1], ah[mt][2], ah[mt][3], bh0, bh1);
                    MMATF32(c[mt][nt], ah[mt][0], ah[mt][1], ah[mt][2], ah[mt][3], bl0, bl1);
                    MMATF32(c[mt][nt], al[mt][0], al[mt][1], al[mt][2], al[mt][3], bh0, bh1);
                }
            }
        }
        __syncthreads();
    }

#pragma unroll
    for (int mt = 0; mt < 4; mt++) {
#pragma unroll
        for (int nt = 0; nt < 8; nt++) {
            int col = n0 + wn * 64 + nt * 8 + 2 * q;
            float2 bb = *reinterpret_cast<const float2*>(bias + col);
#pragma unroll
            for (int half = 0; half < 2; half++) {
                int row = m0 + wm * 64 + mt * 16 + gid + half * 8;
                float v0 = c[mt][nt][half * 2] + bb.x;
                float v1 = c[mt][nt][half * 2 + 1] + bb.y;
                if (MODE == 0) {
                    *reinterpret_cast<float2*>(C + (size_t)row * ldc + col) = make_float2(v0, v1);
                } else {
                    size_t ix = (size_t)row * ldc + col;
                    float2 rr = *reinterpret_cast<const float2*>(aux + ix);
                    float q0 = fsigmoid(v0), q1 = fsigmoid(v1);
                    float zt0 = 0.f, zt1 = 0.f;
                    if (rr.x > 1.0f - q0)
                        zt0 = 2.0f * __logf(fmaxf(rr.x - (1.0f - q0), 0.0f) / q0 * EBM1 + 1.0f);
                    if (rr.y > 1.0f - q1)
                        zt1 = 2.0f * __logf(fmaxf(rr.y - (1.0f - q1), 0.0f) / q1 * EBM1 + 1.0f);
                    *reinterpret_cast<float2*>(C + ix) = make_float2(q0, q1);
                    *reinterpret_cast<float2*>(o1 + ix) = make_float2(zt0, zt1);
                    // o2/o3 point into d_out at +3 floats — 4B-aligned only: scalar stores
                    o2[ix] = zt0 > 0.f ? 1.f : 0.f;
                    o2[ix + 1] = zt1 > 0.f ? 1.f : 0.f;
                    o3[ix] = zt0;
                    o3[ix + 1] = zt1;
                }
            }
        }
    }
}

// ================= bf16 MMA GEMM4 + fused recon-loss =================
#define G4_APITCH 40
#define G4_BPITCH 136
__global__ __launch_bounds__(256)
void gemm4_loss(const __nv_bfloat16* __restrict__ Ahb,
                const __nv_bfloat16* __restrict__ Bw,
                const float* __restrict__ bias,
                const float* __restrict__ X,
                float* __restrict__ part)
{
    __shared__ __nv_bfloat16 Ash[2][128 * G4_APITCH];
    __shared__ __nv_bfloat16 Bsh[2][32 * G4_BPITCH];
    __shared__ float red[256];

    const int tid = threadIdx.x;
    const int lane = tid & 31;
    const int w = tid >> 5;
    const int wm = w & 3;
    const int wnn = (w >> 2) * 64;
    const int m0 = blockIdx.y * 128;
    const int n0 = blockIdx.x * 128;

    const int av_r0 = tid >> 2, av_c0 = (tid & 3) * 8;
    const int av_r1 = (tid + 256) >> 2, av_c1 = ((tid + 256) & 3) * 8;
    const int bv_r0 = tid >> 4, bv_c0 = (tid & 15) * 8;
    const int bv_r1 = (tid + 256) >> 4, bv_c1 = ((tid + 256) & 15) * 8;

    auto load_stage = [&](int buf, int k0) {
        unsigned sa = su32(&Ash[buf][0]);
        CPA16(sa + (av_r0 * G4_APITCH + av_c0) * 2,
              Ahb + (size_t)(m0 + av_r0) * HD + k0 + av_c0);
        CPA16(sa + (av_r1 * G4_APITCH + av_c1) * 2,
              Ahb + (size_t)(m0 + av_r1) * HD + k0 + av_c1);
        unsigned sbm = su32(&Bsh[buf][0]);
        {
            int gc = n0 + bv_c0;
            unsigned sz = (gc < DIN) ? 16u : 0u;
            const __nv_bfloat16* src = Bw + (size_t)(k0 + bv_r0) * DIN + (sz ? gc : 0);
            CPA16Z(sbm + (bv_r0 * G4_BPITCH + bv_c0) * 2, src, sz);
        }
        {
            int gc = n0 + bv_c1;
            unsigned sz = (gc < DIN) ? 16u : 0u;
            const __nv_bfloat16* src = Bw + (size_t)(k0 + bv_r1) * DIN + (sz ? gc : 0);
            CPA16Z(sbm + (bv_r1 * G4_BPITCH + bv_c1) * 2, src, sz);
        }
        CPCOMMIT();
    };

    float c[2][8][4];
#pragma unroll
    for (int i = 0; i < 2; i++)
#pragma unroll
        for (int j = 0; j < 8; j++)
#pragma unroll
            for (int e = 0; e < 4; e++) c[i][j][e] = 0.f;

    const int rA8 = (lane & 7) + 8 * ((lane >> 3) & 1);
    const int cA8 = 8 * (lane >> 4);
    const int rB8 = (lane & 7) + 8 * ((lane >> 3) & 1);
    const int cB8 = 8 * (lane >> 4);

    load_stage(0, 0);
    for (int ks = 0; ks < 16; ks++) {
        CPWAIT0();
        __syncthreads();
        if (ks + 1 < 16) load_stage((ks + 1) & 1, (ks + 1) * 32);
        int buf = ks & 1;
        unsigned abase = su32(&Ash[buf][0]);
        unsigned bbase = su32(&Bsh[buf][0]);
#pragma unroll
        for (int kt = 0; kt < 2; kt++) {
            unsigned a[2][4];
#pragma unroll
            for (int mt = 0; mt < 2; mt++) {
                unsigned addr = abase + ((wm * 32 + mt * 16 + rA8) * G4_APITCH + kt * 16 + cA8) * 2;
                LDSM4(a[mt][0], a[mt][1], a[mt][2], a[mt][3], addr);
            }
#pragma unroll
            for (int ntp = 0; ntp < 4; ntp++) {
                unsigned b0, b1, b2, b3;
                unsigned addr = bbase + ((kt * 16 + rB8) * G4_BPITCH + wnn + ntp * 16 + cB8) * 2;
                LDSM4T(b0, b1, b2, b3, addr);
#pragma unroll
                for (int mt = 0; mt < 2; mt++) {
                    MMA16816(c[mt][2 * ntp], a[mt][0], a[mt][1], a[mt][2], a[mt][3], b0, b1);
                    MMA16816(c[mt][2 * ntp + 1], a[mt][0], a[mt][1], a[mt][2], a[mt][3], b2, b3);
                }
            }
        }
        __syncthreads();
    }

    float lsum = 0.f;
    const int gid = lane >> 2;
    const int cpair = (lane & 3) << 1;
#pragma unroll
    for (int mt = 0; mt < 2; mt++) {
#pragma unroll
        for (int nt = 0; nt < 8; nt++) {
            int col = n0 + wnn + nt * 8 + cpair;
            if (col < DIN) {
                float b0v = bias[col], b1v = bias[col + 1];
#pragma unroll
                for (int half = 0; half < 2; half++) {
                    int row = m0 + wm * 32 + mt * 16 + gid + half * 8;
                    float2 xx = *reinterpret_cast<const float2*>(X + (size_t)row * DIN + col);
                    float d0 = c[mt][nt][half * 2] + b0v - xx.x;
                    float d1 = c[mt][nt][half * 2 + 1] + b1v - xx.y;
                    lsum += d0 * d0 + d1 * d1;
                }
            }
        }
    }
    red[tid] = lsum;
    __syncthreads();
#pragma unroll
    for (int s = 128; s > 0; s >>= 1) {
        if (tid < s) red[tid] += red[tid + s];
        __syncthreads();
    }
    if (tid == 0) part[blockIdx.y * gridDim.x + blockIdx.x] = red[0];
}

// ================= fused 30-step Gibbs v2: warp-per-32-columns (B traffic /8) =================
#define GR 128
#define WP 264
#define ZP 264
__global__ __launch_bounds__(256)
void gibbs_fused(const float* __restrict__ z_init, const float* __restrict__ grnd,
                 const float* __restrict__ rbm_h, const float* __restrict__ rbm_W,
                 float* __restrict__ zout)
{
    extern __shared__ __align__(16) unsigned char smraw[];
    __nv_bfloat16* Wsh = reinterpret_cast<__nv_bfloat16*>(smraw);
    __nv_bfloat16* Zs = Wsh + 256 * WP;
    float* hsh = reinterpret_cast<float*>(Zs + GR * ZP);

    const int tid = threadIdx.x;
    const int lane = tid & 31;
    const int w = tid >> 5;
    const int rowBase = blockIdx.x * GR;

    for (int i = tid; i < 256 * 256; i += 256) {
        int rr = i >> 8, cc = i & 255;
        Wsh[rr * WP + cc] = __float2bfloat16_rn(rbm_W[i]);
    }
    if (tid < 256) hsh[tid] = rbm_h[tid];
    for (int i = tid; i < GR * 256; i += 256) {
        int rr = i >> 8, cc = i & 255;
        Zs[rr * ZP + cc] = __float2bfloat16_rn(z_init[(size_t)(rowBase + rr) * LD + cc]);
    }
    __syncthreads();

    const int rA8 = (lane & 7) + 8 * ((lane >> 3) & 1);
    const int cA8 = 8 * (lane >> 4);
    const int rB8 = (lane & 7) + 8 * ((lane >> 3) & 1);
    const int cB8 = 8 * (lane >> 4);
    const int gid = lane >> 2;
    const int cpair = (lane & 3) << 1;
    const int wc = w << 5;                 // warp's 32-column slice

    unsigned abase = su32(Zs);
    unsigned bbase = su32(Wsh);

    for (int t = 0; t < 30; t++) {
        float c[8][4][4];                  // [row-group][col-group of 8][frag]
#pragma unroll
        for (int i = 0; i < 8; i++)
#pragma unroll
            for (int j = 0; j < 4; j++)
#pragma unroll
                for (int e = 0; e < 4; e++) c[i][j][e] = 0.f;

#pragma unroll 2
        for (int k0 = 0; k0 < 256; k0 += 16) {
            unsigned a[8][4];
#pragma unroll
            for (int mg = 0; mg < 8; mg++)
                LDSM4(a[mg][0], a[mg][1], a[mg][2], a[mg][3],
                      abase + (((mg << 4) + rA8) * ZP + k0 + cA8) * 2);
#pragma unroll
            for (int cg = 0; cg < 2; cg++) {
                unsigned b0, b1, b2, b3;
                LDSM4T(b0, b1, b2, b3,
                       bbase + ((k0 + rB8) * WP + wc + cg * 16 + cB8) * 2);
#pragma unroll
                for (int mg = 0; mg < 8; mg++) {
                    MMA16816(c[mg][2 * cg], a[mg][0], a[mg][1], a[mg][2], a[mg][3], b0, b1);
                    MMA16816(c[mg][2 * cg + 1], a[mg][0], a[mg][1], a[mg][2], a[mg][3], b2, b3);
                }
            }
        }
        __syncthreads();   // all warps done READING Zs

        // epilogue: r < sigmoid(x) ⟺ r + r*e^{-x} < 1
#pragma unroll
        for (int mg = 0; mg < 8; mg++) {
#pragma unroll
            for (int ng = 0; ng < 4; ng++) {
                int col = wc + ng * 8 + cpair;
                float h0 = hsh[col], h1 = hsh[col + 1];
#pragma unroll
                for (int half = 0; half < 2; half++) {
                    int rloc = (mg << 4) + gid + half * 8;
                    size_t gro = ((size_t)t * BQ + rowBase + rloc) * LD + col;
                    float2 rr = *reinterpret_cast<const float2*>(grnd + gro);
                    float e0 = __expf(-(h0 + c[mg][ng][half * 2]));
                    float e1 = __expf(-(h1 + c[mg][ng][half * 2 + 1]));
                    float z0f = (fmaf(rr.x, e0, rr.x) < 1.f) ? 1.f : 0.f;
                    float z1f = (fmaf(rr.y, e1, rr.y) < 1.f) ? 1.f : 0.f;
                    if (t == 29) {
                        *reinterpret_cast<float2*>(zout + (size_t)(rowBase + rloc) * LD + col) =
                            make_float2(z0f, z1f);
                    } else {
                        __nv_bfloat162 pz;
                        pz.x = __float2bfloat16_rn(z0f);
                        pz.y = __float2bfloat16_rn(z1f);
                        *reinterpret_cast<__nv_bfloat162*>(Zs + rloc * ZP + col) = pz;
                    }
                }
            }
        }
        __syncthreads();   // writes visible before next step's reads
    }
}

// ================= BN =================
__global__ void bn_stats_part(const float* __restrict__ Hb)
{
    int col = blockIdx.x * 32 + threadIdx.x;
    int r0 = blockIdx.y * (BQ / 16);
    float s = 0.f, ss = 0.f;
    for (int r = threadIdx.y; r < BQ / 16; r += 8) {
        float v = Hb[(size_t)(r0 + r) * HD + col];
        s += v; ss += v * v;
    }
    __shared__ float sh[8][32], sh2[8][32];
    sh[threadIdx.y][threadIdx.x] = s;
    sh2[threadIdx.y][threadIdx.x] = ss;
    __syncthreads();
    if (threadIdx.y == 0) {
        float ts = 0.f, tss = 0.f;
#pragma unroll
        for (int y = 0; y < 8; y++) { ts += sh[y][threadIdx.x]; tss += sh2[y][threadIdx.x]; }
        g_ps[blockIdx.y * HD + col] = ts;
        g_pss[blockIdx.y * HD + col] = tss;
    }
}

__global__ void bn_final(const float* __restrict__ g, const float* __restrict__ be)
{
    int c = blockIdx.x * 256 + threadIdx.x;
    if (c < HD) {
        float s = 0.f, ss = 0.f;
#pragma unroll
        for (int p = 0; p < 16; p++) { s += g_ps[p * HD + c]; ss += g_pss[p * HD + c]; }
        float mu = s / (float)BQ;
        float var = ss / (float)BQ - mu * mu;
        float sc = g[c] * rsqrtf(var + 1e-5f);
        g_scale[c] = sc;
        g_shift[c] = be[c] - mu * sc;
    }
}

template <int WB>
__global__ void bn_relu()
{
    size_t i = ((size_t)blockIdx.x * 256 + threadIdx.x) * 4;
    float4 v = *reinterpret_cast<float4*>(&g_h[i]);
    int c = (int)(i & (HD - 1));
    v.x = fmaxf(v.x * g_scale[c + 0] + g_shift[c + 0], 0.f);
    v.y = fmaxf(v.y * g_scale[c + 1] + g_shift[c + 1], 0.f);
    v.z = fmaxf(v.z * g_scale[c + 2] + g_shift[c + 2], 0.f);
    v.w = fmaxf(v.w * g_scale[c + 3] + g_shift[c + 3], 0.f);
    if (WB) {
        __nv_bfloat162 p0, p1;
        p0.x = __float2bfloat16_rn(v.x); p0.y = __float2bfloat16_rn(v.y);
        p1.x = __float2bfloat16_rn(v.z); p1.y = __float2bfloat16_rn(v.w);
        *reinterpret_cast<__nv_bfloat162*>(&g_hb[i]) = p0;
        *reinterpret_cast<__nv_bfloat162*>(&g_hb[i + 2]) = p1;
    } else {
        *reinterpret_cast<float4*>(&g_h[i]) = v;
    }
}

__global__ void cvt_w2(const float* __restrict__ w)
{
    int i = blockIdx.x * 256 + threadIdx.x;
    if (i < HD * DIN) g_w2b[i] = __float2bfloat16_rn(w[i]);
}

// ================= KL rows =================
__global__ __launch_bounds__(256)
void kl_rows(const float* __restrict__ Z, const float* __restrict__ Q,
             const float* __restrict__ h, const float* __restrict__ W,
             float* __restrict__ orow, int useQ)
{
    __shared__ unsigned long long zp[8][LD];
    __shared__ float wpart[16][8];
    const int tid = threadIdx.x;
    const int lane = tid & 31;
    const int w = tid >> 5;
    const int j = tid;
    const int r0 = blockIdx.x * 16;

    for (int idx = tid; idx < 8 * LD; idx += 256) {
        int rp = idx >> 8, i = idx & 255;
        float za = Z[(size_t)(r0 + 2 * rp) * LD + i];
        float zb = Z[(size_t)(r0 + 2 * rp + 1) * LD + i];
        unsigned long long pk;
        asm("mov.b64 %0, {%1,%2};" : "=l"(pk) : "f"(za), "f"(zb));
        zp[rp][i] = pk;
    }
    __syncthreads();

    unsigned long long acc[8];
#pragma unroll
    for (int rp = 0; rp < 8; rp++) acc[rp] = 0ULL;
    for (int i = 0; i < LD; i++) {
        float wv = W[i * LD + j];
        unsigned long long ww;
        asm("mov.b64 %0, {%1,%1};" : "=l"(ww) : "f"(wv));
#pragma unroll
        for (int rp = 0; rp < 8; rp++)
            asm("fma.rn.f32x2 %0, %1, %2, %0;" : "+l"(acc[rp]) : "l"(zp[rp][i]), "l"(ww));
    }

    float hj = h[j];
#pragma unroll
    for (int rp = 0; rp < 8; rp++) {
        float aA, aB, zA, zB;
        asm("mov.b64 {%0,%1}, %2;" : "=f"(aA), "=f"(aB) : "l"(acc[rp]));
        asm("mov.b64 {%0,%1}, %2;" : "=f"(zA), "=f"(zB) : "l"(zp[rp][j]));
#pragma unroll
        for (int half = 0; half < 2; half++) {
            int r = 2 * rp + half;
            float zj = half ? zB : zA;
            float av = half ? aB : aA;
            float val = zj * (hj + av);
            if (useQ) {
                float qv = Q[(size_t)(r0 + r) * LD + j];
                qv = fminf(fmaxf(qv, 1e-7f), 1.0f - 1e-7f);
                val += (zj > 0.5f) ? __logf(qv) : __logf(1.0f - qv);
            }
#pragma unroll
            for (int s = 16; s > 0; s >>= 1)
                val += __shfl_down_sync(0xffffffffu, val, s);
            if (lane == 0) wpart[r][w] = val;
        }
    }
    __syncthreads();
    if (tid < 16) {
        float s = 0.f;
#pragma unroll
        for (int k = 0; k < 8; k++) s += wpart[tid][k];
        orow[r0 + tid] = s;
    }
}

__global__ void finalize_k(float* __restrict__ out)
{
    __shared__ float red[256];
    int t = threadIdx.x;
    float res[3];
    const float* srcs[3] = {g_part, g_rowpos, g_rowneg};
    int cnts[3] = {4096, BQ, BQ};
#pragma unroll
    for (int p = 0; p < 3; p++) {
        float s = 0.f;
        for (int i = t; i < cnts[p]; i += 256) s += srcs[p][i];
        red[t] = s;
        __syncthreads();
#pragma unroll
        for (int k = 128; k > 0; k >>= 1) {
            if (t < k) red[t] += red[t + k];
            __syncthreads();
        }
        res[p] = red[0];
        __syncthreads();
    }
    if (t == 0) {
        float recon = res[0] / (float)BQ;
        float kl = res[1] / (float)BQ + res[2] / (float)BQ;
        out[0] = -recon - 0.001f * kl;
        out[1] = recon;
        out[2] = kl;
    }
}

extern "C" void kernel_launch(void* const* d_in, const int* in_sizes, int n_in,
                              void* d_out, int out_size)
{
    const float* x      = (const float*)d_in[0];
    const float* rho    = (const float*)d_in[1];
    const float* z_init = (const float*)d_in[2];
    const float* grnd   = (const float*)d_in[3];
    const float* eW1    = (const float*)d_in[4];
    const float* eb1    = (const float*)d_in[5];
    const float* eg1    = (const float*)d_in[6];
    const float* ebe1   = (const float*)d_in[7];
    const float* eW2    = (const float*)d_in[8];
    const float* eb2    = (const float*)d_in[9];
    const float* dW1    = (const float*)d_in[10];
    const float* db1    = (const float*)d_in[11];
    const float* dg1    = (const float*)d_in[12];
    const float* dbe1   = (const float*)d_in[13];
    const float* dW2    = (const float*)d_in[14];
    const float* db2    = (const float*)d_in[15];
    const float* rbm_h  = (const float*)d_in[16];
    const float* rbm_W  = (const float*)d_in[17];

    float* out = (float*)d_out;
    float* out_z = out + 3;
    float* out_zeta = out + 3 + (size_t)BQ * LD;

    float *p_h, *p_q, *p_zeta, *p_zb, *p_rp, *p_rn, *p_part;
    __nv_bfloat16 *p_hb, *p_w2b;
    cudaGetSymbolAddress((void**)&p_h, g_h);
    cudaGetSymbolAddress((void**)&p_hb, g_hb);
    cudaGetSymbolAddress((void**)&p_w2b, g_w2b);
    cudaGetSymbolAddress((void**)&p_q, g_q);
    cudaGetSymbolAddress((void**)&p_zeta, g_zeta);
    cudaGetSymbolAddress((void**)&p_zb, g_zb);
    cudaGetSymbolAddress((void**)&p_rp, g_rowpos);
    cudaGetSymbolAddress((void**)&p_rn, g_rowneg);
    cudaGetSymbolAddress((void**)&p_part, g_part);

    int gibbs_smem = (256 * WP + GR * ZP) * 2 + 256 * 4;
    cudaFuncSetAttribute(gibbs_fused, cudaFuncAttributeMaxDynamicSharedMemorySize, gibbs_smem);
    cudaFuncSetAttribute(gemm_v2<0>, cudaFuncAttributeMaxDynamicSharedMemorySize, V2_SMEM);
    cudaFuncSetAttribute(gemm_v2<1>, cudaFuncAttributeMaxDynamicSharedMemorySize, V2_SMEM);

    // serial; launch #4 = gibbs_fused (verify the L1-reduction prediction)
    cvt_w2<<<(HD * DIN + 255) / 256, 256>>>(dW2);                                        // 1
    gemm_v2<0><<<dim3(2, 128), 256, V2_SMEM>>>(x, DIN, eW1, HD, eb1, p_h, HD, DIN,
                                               nullptr, nullptr, nullptr, nullptr);      // 2  G1
    bn_stats_part<<<dim3(16, 16), dim3(32, 8)>>>(p_h);                                   // 3
    gibbs_fused<<<BQ / GR, 256, gibbs_smem>>>(z_init, grnd, rbm_h, rbm_W, p_zb);         // 4  <- ncu
    bn_final<<<2, 256>>>(eg1, ebe1);                                                     // 5
    bn_relu<0><<<8192, 256>>>();                                                         // 6
    gemm_v2<1><<<dim3(1, 128), 256, V2_SMEM>>>(p_h, HD, eW2, LD, eb2, p_q, LD, HD,
                                               rho, p_zeta, out_z, out_zeta);            // 7  G2
    kl_rows<<<1024, 256>>>(out_z, p_q, rbm_h, rbm_W, p_rp, 1);                           // 8
    kl_rows<<<1024, 256>>>(p_zb, nullptr, rbm_h, rbm_W, p_rn, 0);                        // 9
    gemm_v2<0><<<dim3(2, 128), 256, V2_SMEM>>>(p_zeta, LD, dW1, HD, db1, p_h, HD, LD,
                                               nullptr, nullptr, nullptr, nullptr);      // 10 G3
    bn_stats_part<<<dim3(16, 16), dim3(32, 8)>>>(p_h);                                   // 11
    bn_final<<<2, 256>>>(dg1, dbe1);                                                     // 12
    bn_relu<1><<<8192, 256>>>();                                                         // 13
    gemm4_loss<<<dim3(32, 128), 256>>>(p_hb, p_w2b, db2, x, p_part);                     // 14
    finalize_k<<<1, 256>>>(out);                                                         // 15
}

// round 17
// speedup vs baseline: 1.0039x; 1.0039x over previous
#include <cuda_runtime.h>
#include <cuda_bf16.h>
#include <math.h>

#define BQ 16384
#define DIN 4000
#define HD 512
#define LD 256
#define EBM1 0.6487212707001282f  // exp(0.5)-1

__device__ float g_h[(size_t)BQ * HD];
__device__ __nv_bfloat16 g_hb[(size_t)BQ * HD];
__device__ __nv_bfloat16 g_w2b[(size_t)HD * DIN];
__device__ float g_q[(size_t)BQ * LD];
__device__ float g_zeta[(size_t)BQ * LD];
__device__ float g_zb[(size_t)BQ * LD];
__device__ float g_rowpos[BQ];
__device__ float g_rowneg[BQ];
__device__ float g_part[4096];
__device__ float g_ps[16 * HD];
__device__ float g_pss[16 * HD];
__device__ float g_scale[HD];
__device__ float g_shift[HD];

__device__ __forceinline__ float fsigmoid(float x) { return 1.0f / (1.0f + expf(-x)); }
__device__ __forceinline__ unsigned su32(const void* p) { return (unsigned)__cvta_generic_to_shared(p); }

#define LDSM4(a0,a1,a2,a3,addr) \
    asm volatile("ldmatrix.sync.aligned.m8n8.x4.shared.b16 {%0,%1,%2,%3},[%4];" \
                 : "=r"(a0),"=r"(a1),"=r"(a2),"=r"(a3) : "r"(addr))
#define LDSM4T(a0,a1,a2,a3,addr) \
    asm volatile("ldmatrix.sync.aligned.m8n8.x4.trans.shared.b16 {%0,%1,%2,%3},[%4];" \
                 : "=r"(a0),"=r"(a1),"=r"(a2),"=r"(a3) : "r"(addr))
#define MMA16816(c,a0,a1,a2,a3,b0,b1) \
    asm volatile("mma.sync.aligned.m16n8k16.row.col.f32.bf16.bf16.f32 " \
                 "{%0,%1,%2,%3},{%4,%5,%6,%7},{%8,%9},{%0,%1,%2,%3};" \
                 : "+f"((c)[0]),"+f"((c)[1]),"+f"((c)[2]),"+f"((c)[3]) \
                 : "r"(a0),"r"(a1),"r"(a2),"r"(a3),"r"(b0),"r"(b1))
#define MMATF32(c,a0,a1,a2,a3,b0,b1) \
    asm volatile("mma.sync.aligned.m16n8k8.row.col.f32.tf32.tf32.f32 " \
                 "{%0,%1,%2,%3},{%4,%5,%6,%7},{%8,%9},{%0,%1,%2,%3};" \
                 : "+f"((c)[0]),"+f"((c)[1]),"+f"((c)[2]),"+f"((c)[3]) \
                 : "r"(a0),"r"(a1),"r"(a2),"r"(a3),"r"(b0),"r"(b1))
#define CPA16(s,g)      asm volatile("cp.async.cg.shared.global [%0],[%1],16;" :: "r"(s),"l"(g))
#define CPA16Z(s,g,sz)  asm volatile("cp.async.cg.shared.global [%0],[%1],16,%2;" :: "r"(s),"l"(g),"r"(sz))
#define CPCOMMIT()      asm volatile("cp.async.commit_group;")
#define CPWAIT0()       asm volatile("cp.async.wait_group 0;")

__device__ __forceinline__ void tf32_split_u(float x, unsigned& hi, unsigned& lo) {
    asm("cvt.rna.tf32.f32 %0,%1;" : "=r"(hi) : "f"(x));
    float lf = x - __uint_as_float(hi);
    asm("cvt.rna.tf32.f32 %0,%1;" : "=r"(lo) : "f"(lf));
}

// ================= tf32x3 GEMM v2: 128x256 block, 64x64 warp tiles =================
#define V2_PA 20
#define V2_PB 260
#define V2_NSMA (128 * V2_PA)
#define V2_NSMB (16 * V2_PB)
#define V2_SMEM ((2 * (V2_NSMA + V2_NSMB)) * 4)

template <int MODE>
__global__ __launch_bounds__(256)
void gemm_v2(const float* __restrict__ A, int lda,
             const float* __restrict__ B, int ldb,
             const float* __restrict__ bias,
             float* __restrict__ C, int ldc, int K,
             const float* __restrict__ aux,
             float* __restrict__ o1, float* __restrict__ o2, float* __restrict__ o3)
{
    extern __shared__ __align__(16) float smv2[];
    float* Asm = smv2;
    float* Bsm = smv2 + 2 * V2_NSMA;

    const int tid = threadIdx.x;
    const int lane = tid & 31;
    const int w = tid >> 5;
    const int wm = w & 1;
    const int wn = w >> 1;
    const int m0 = blockIdx.y * 128;
    const int n0 = blockIdx.x * 256;
    const int gid = lane >> 2, q = lane & 3;

    const int arow0 = tid >> 2, ac0 = (tid & 3) * 4;
    const int arow1 = (tid + 256) >> 2, ac1 = ((tid + 256) & 3) * 4;

    auto load_stage = [&](int buf, int k0) {
        unsigned sa = su32(Asm + buf * V2_NSMA);
        CPA16(sa + (arow0 * V2_PA + ac0) * 4, A + (size_t)(m0 + arow0) * lda + k0 + ac0);
        CPA16(sa + (arow1 * V2_PA + ac1) * 4, A + (size_t)(m0 + arow1) * lda + k0 + ac1);
        unsigned sb2 = su32(Bsm + buf * V2_NSMB);
#pragma unroll
        for (int i = 0; i < 4; i++) {
            int cb = tid + i * 256;
            int brow = cb >> 6, bc = (cb & 63) * 4;
            CPA16(sb2 + (brow * V2_PB + bc) * 4, B + (size_t)(k0 + brow) * ldb + n0 + bc);
        }
        CPCOMMIT();
    };

    float c[4][8][4];
#pragma unroll
    for (int i = 0; i < 4; i++)
#pragma unroll
        for (int j = 0; j < 8; j++)
#pragma unroll
            for (int e = 0; e < 4; e++) c[i][j][e] = 0.f;

    const int NS = K / 16;
    load_stage(0, 0);
    for (int s = 0; s < NS; s++) {
        CPWAIT0();
        __syncthreads();
        if (s + 1 < NS) load_stage((s + 1) & 1, (s + 1) * 16);
        const float* As = Asm + (s & 1) * V2_NSMA;
        const float* Bs = Bsm + (s & 1) * V2_NSMB;
#pragma unroll
        for (int ks = 0; ks < 2; ks++) {
            const int kb = ks * 8;
            unsigned ah[4][4], al[4][4];
#pragma unroll
            for (int mt = 0; mt < 4; mt++) {
                const int mB = wm * 64 + mt * 16;
                float r0 = As[(mB + gid) * V2_PA + kb + q];
                float r1 = As[(mB + gid + 8) * V2_PA + kb + q];
                float r2 = As[(mB + gid) * V2_PA + kb + 4 + q];
                float r3 = As[(mB + gid + 8) * V2_PA + kb + 4 + q];
                tf32_split_u(r0, ah[mt][0], al[mt][0]);
                tf32_split_u(r1, ah[mt][1], al[mt][1]);
                tf32_split_u(r2, ah[mt][2], al[mt][2]);
                tf32_split_u(r3, ah[mt][3], al[mt][3]);
            }
#pragma unroll
            for (int nt = 0; nt < 8; nt++) {
                const int nB = wn * 64 + nt * 8;
                float b0 = Bs[(kb + q) * V2_PB + nB + gid];
                float b1 = Bs[(kb + 4 + q) * V2_PB + nB + gid];
                unsigned bh0, bl0, bh1, bl1;
                tf32_split_u(b0, bh0, bl0);
                tf32_split_u(b1, bh1, bl1);
#pragma unroll
                for (int mt = 0; mt < 4; mt++) {
                    MMATF32(c[mt][nt], ah[mt][0], ah[mt][1], ah[mt][2], ah[mt][3], bh0, bh1);
                    MMATF32(c[mt][nt], ah[mt][0], ah[mt][1], ah[mt][2], ah[mt][3], bl0, bl1);
                    MMATF32(c[mt][nt], al[mt][0], al[mt][1], al[mt][2], al[mt][3], bh0, bh1);
                }
            }
        }
        __syncthreads();
    }

#pragma unroll
    for (int mt = 0; mt < 4; mt++) {
#pragma unroll
        for (int nt = 0; nt < 8; nt++) {
            int col = n0 + wn * 64 + nt * 8 + 2 * q;
            float2 bb = *reinterpret_cast<const float2*>(bias + col);
#pragma unroll
            for (int half = 0; half < 2; half++) {
                int row = m0 + wm * 64 + mt * 16 + gid + half * 8;
                float v0 = c[mt][nt][half * 2] + bb.x;
                float v1 = c[mt][nt][half * 2 + 1] + bb.y;
                if (MODE == 0) {
                    *reinterpret_cast<float2*>(C + (size_t)row * ldc + col) = make_float2(v0, v1);
                } else {
                    size_t ix = (size_t)row * ldc + col;
                    float2 rr = *reinterpret_cast<const float2*>(aux + ix);
                    float q0 = fsigmoid(v0), q1 = fsigmoid(v1);
                    float zt0 = 0.f, zt1 = 0.f;
                    if (rr.x > 1.0f - q0)
                        zt0 = 2.0f * __logf(fmaxf(rr.x - (1.0f - q0), 0.0f) / q0 * EBM1 + 1.0f);
                    if (rr.y > 1.0f - q1)
                        zt1 = 2.0f * __logf(fmaxf(rr.y - (1.0f - q1), 0.0f) / q1 * EBM1 + 1.0f);
                    *reinterpret_cast<float2*>(C + ix) = make_float2(q0, q1);
                    *reinterpret_cast<float2*>(o1 + ix) = make_float2(zt0, zt1);
                    // o2/o3 point into d_out at +3 floats — 4B-aligned only: scalar stores
                    o2[ix] = zt0 > 0.f ? 1.f : 0.f;
                    o2[ix + 1] = zt1 > 0.f ? 1.f : 0.f;
                    o3[ix] = zt0;
                    o3[ix + 1] = zt1;
                }
            }
        }
    }
}

// ================= bf16 MMA GEMM4 + fused recon-loss =================
#define G4_APITCH 40
#define G4_BPITCH 136
__global__ __launch_bounds__(256)
void gemm4_loss(const __nv_bfloat16* __restrict__ Ahb,
                const __nv_bfloat16* __restrict__ Bw,
                const float* __restrict__ bias,
                const float* __restrict__ X,
                float* __restrict__ part)
{
    __shared__ __nv_bfloat16 Ash[2][128 * G4_APITCH];
    __shared__ __nv_bfloat16 Bsh[2][32 * G4_BPITCH];
    __shared__ float red[256];

    const int tid = threadIdx.x;
    const int lane = tid & 31;
    const int w = tid >> 5;
    const int wm = w & 3;
    const int wnn = (w >> 2) * 64;
    const int m0 = blockIdx.y * 128;
    const int n0 = blockIdx.x * 128;

    const int av_r0 = tid >> 2, av_c0 = (tid & 3) * 8;
    const int av_r1 = (tid + 256) >> 2, av_c1 = ((tid + 256) & 3) * 8;
    const int bv_r0 = tid >> 4, bv_c0 = (tid & 15) * 8;
    const int bv_r1 = (tid + 256) >> 4, bv_c1 = ((tid + 256) & 15) * 8;

    auto load_stage = [&](int buf, int k0) {
        unsigned sa = su32(&Ash[buf][0]);
        CPA16(sa + (av_r0 * G4_APITCH + av_c0) * 2,
              Ahb + (size_t)(m0 + av_r0) * HD + k0 + av_c0);
        CPA16(sa + (av_r1 * G4_APITCH + av_c1) * 2,
              Ahb + (size_t)(m0 + av_r1) * HD + k0 + av_c1);
        unsigned sbm = su32(&Bsh[buf][0]);
        {
            int gc = n0 + bv_c0;
            unsigned sz = (gc < DIN) ? 16u : 0u;
            const __nv_bfloat16* src = Bw + (size_t)(k0 + bv_r0) * DIN + (sz ? gc : 0);
            CPA16Z(sbm + (bv_r0 * G4_BPITCH + bv_c0) * 2, src, sz);
        }
        {
            int gc = n0 + bv_c1;
            unsigned sz = (gc < DIN) ? 16u : 0u;
            const __nv_bfloat16* src = Bw + (size_t)(k0 + bv_r1) * DIN + (sz ? gc : 0);
            CPA16Z(sbm + (bv_r1 * G4_BPITCH + bv_c1) * 2, src, sz);
        }
        CPCOMMIT();
    };

    float c[2][8][4];
#pragma unroll
    for (int i = 0; i < 2; i++)
#pragma unroll
        for (int j = 0; j < 8; j++)
#pragma unroll
            for (int e = 0; e < 4; e++) c[i][j][e] = 0.f;

    const int rA8 = (lane & 7) + 8 * ((lane >> 3) & 1);
    const int cA8 = 8 * (lane >> 4);
    const int rB8 = (lane & 7) + 8 * ((lane >> 3) & 1);
    const int cB8 = 8 * (lane >> 4);

    load_stage(0, 0);
    for (int ks = 0; ks < 16; ks++) {
        CPWAIT0();
        __syncthreads();
        if (ks + 1 < 16) load_stage((ks + 1) & 1, (ks + 1) * 32);
        int buf = ks & 1;
        unsigned abase = su32(&Ash[buf][0]);
        unsigned bbase = su32(&Bsh[buf][0]);
#pragma unroll
        for (int kt = 0; kt < 2; kt++) {
            unsigned a[2][4];
#pragma unroll
            for (int mt = 0; mt < 2; mt++) {
                unsigned addr = abase + ((wm * 32 + mt * 16 + rA8) * G4_APITCH + kt * 16 + cA8) * 2;
                LDSM4(a[mt][0], a[mt][1], a[mt][2], a[mt][3], addr);
            }
#pragma unroll
            for (int ntp = 0; ntp < 4; ntp++) {
                unsigned b0, b1, b2, b3;
                unsigned addr = bbase + ((kt * 16 + rB8) * G4_BPITCH + wnn + ntp * 16 + cB8) * 2;
                LDSM4T(b0, b1, b2, b3, addr);
#pragma unroll
                for (int mt = 0; mt < 2; mt++) {
                    MMA16816(c[mt][2 * ntp], a[mt][0], a[mt][1], a[mt][2], a[mt][3], b0, b1);
                    MMA16816(c[mt][2 * ntp + 1], a[mt][0], a[mt][1], a[mt][2], a[mt][3], b2, b3);
                }
            }
        }
        __syncthreads();
    }

    float lsum = 0.f;
    const int gid = lane >> 2;
    const int cpair = (lane & 3) << 1;
#pragma unroll
    for (int mt = 0; mt < 2; mt++) {
#pragma unroll
        for (int nt = 0; nt < 8; nt++) {
            int col = n0 + wnn + nt * 8 + cpair;
            if (col < DIN) {
                float b0v = bias[col], b1v = bias[col + 1];
#pragma unroll
                for (int half = 0; half < 2; half++) {
                    int row = m0 + wm * 32 + mt * 16 + gid + half * 8;
                    float2 xx = *reinterpret_cast<const float2*>(X + (size_t)row * DIN + col);
                    float d0 = c[mt][nt][half * 2] + b0v - xx.x;
                    float d1 = c[mt][nt][half * 2 + 1] + b1v - xx.y;
                    lsum += d0 * d0 + d1 * d1;
                }
            }
        }
    }
    red[tid] = lsum;
    __syncthreads();
#pragma unroll
    for (int s = 128; s > 0; s >>= 1) {
        if (tid < s) red[tid] += red[tid + s];
        __syncthreads();
    }
    if (tid == 0) part[blockIdx.y * gridDim.x + blockIdx.x] = red[0];
}

// ================= fused 30-step Gibbs v2: warp-per-32-columns (B traffic /8) =================
#define GR 128
#define WP 264
#define ZP 264
__global__ __launch_bounds__(256)
void gibbs_fused(const float* __restrict__ z_init, const float* __restrict__ grnd,
                 const float* __restrict__ rbm_h, const float* __restrict__ rbm_W,
                 float* __restrict__ zout)
{
    extern __shared__ __align__(16) unsigned char smraw[];
    __nv_bfloat16* Wsh = reinterpret_cast<__nv_bfloat16*>(smraw);
    __nv_bfloat16* Zs = Wsh + 256 * WP;
    float* hsh = reinterpret_cast<float*>(Zs + GR * ZP);

    const int tid = threadIdx.x;
    const int lane = tid & 31;
    const int w = tid >> 5;
    const int rowBase = blockIdx.x * GR;

    for (int i = tid; i < 256 * 256; i += 256) {
        int rr = i >> 8, cc = i & 255;
        Wsh[rr * WP + cc] = __float2bfloat16_rn(rbm_W[i]);
    }
    if (tid < 256) hsh[tid] = rbm_h[tid];
    for (int i = tid; i < GR * 256; i += 256) {
        int rr = i >> 8, cc = i & 255;
        Zs[rr * ZP + cc] = __float2bfloat16_rn(z_init[(size_t)(rowBase + rr) * LD + cc]);
    }
    __syncthreads();

    const int rA8 = (lane & 7) + 8 * ((lane >> 3) & 1);
    const int cA8 = 8 * (lane >> 4);
    const int rB8 = (lane & 7) + 8 * ((lane >> 3) & 1);
    const int cB8 = 8 * (lane >> 4);
    const int gid = lane >> 2;
    const int cpair = (lane & 3) << 1;
    const int wc = w << 5;                 // warp's 32-column slice

    unsigned abase = su32(Zs);
    unsigned bbase = su32(Wsh);

    for (int t = 0; t < 30; t++) {
        float c[8][4][4];                  // [row-group][col-group of 8][frag]
#pragma unroll
        for (int i = 0; i < 8; i++)
#pragma unroll
            for (int j = 0; j < 4; j++)
#pragma unroll
                for (int e = 0; e < 4; e++) c[i][j][e] = 0.f;

#pragma unroll 2
        for (int k0 = 0; k0 < 256; k0 += 16) {
            unsigned a[8][4];
#pragma unroll
            for (int mg = 0; mg < 8; mg++)
                LDSM4(a[mg][0], a[mg][1], a[mg][2], a[mg][3],
                      abase + (((mg << 4) + rA8) * ZP + k0 + cA8) * 2);
#pragma unroll
            for (int cg = 0; cg < 2; cg++) {
                unsigned b0, b1, b2, b3;
                LDSM4T(b0, b1, b2, b3,
                       bbase + ((k0 + rB8) * WP + wc + cg * 16 + cB8) * 2);
#pragma unroll
                for (int mg = 0; mg < 8; mg++) {
                    MMA16816(c[mg][2 * cg], a[mg][0], a[mg][1], a[mg][2], a[mg][3], b0, b1);
                    MMA16816(c[mg][2 * cg + 1], a[mg][0], a[mg][1], a[mg][2], a[mg][3], b2, b3);
                }
            }
        }
        __syncthreads();   // all warps done READING Zs

        // epilogue: r < sigmoid(x) ⟺ r + r*e^{-x} < 1
#pragma unroll
        for (int mg = 0; mg < 8; mg++) {
#pragma unroll
            for (int ng = 0; ng < 4; ng++) {
                int col = wc + ng * 8 + cpair;
                float h0 = hsh[col], h1 = hsh[col + 1];
#pragma unroll
                for (int half = 0; half < 2; half++) {
                    int rloc = (mg << 4) + gid + half * 8;
                    size_t gro = ((size_t)t * BQ + rowBase + rloc) * LD + col;
                    float2 rr = *reinterpret_cast<const float2*>(grnd + gro);
                    float e0 = __expf(-(h0 + c[mg][ng][half * 2]));
                    float e1 = __expf(-(h1 + c[mg][ng][half * 2 + 1]));
                    float z0f = (fmaf(rr.x, e0, rr.x) < 1.f) ? 1.f : 0.f;
                    float z1f = (fmaf(rr.y, e1, rr.y) < 1.f) ? 1.f : 0.f;
                    if (t == 29) {
                        *reinterpret_cast<float2*>(zout + (size_t)(rowBase + rloc) * LD + col) =
                            make_float2(z0f, z1f);
                    } else {
                        __nv_bfloat162 pz;
                        pz.x = __float2bfloat16_rn(z0f);
                        pz.y = __float2bfloat16_rn(z1f);
                        *reinterpret_cast<__nv_bfloat162*>(Zs + rloc * ZP + col) = pz;
                    }
                }
            }
        }
        __syncthreads();   // writes visible before next step's reads
    }
}

// ================= BN =================
__global__ void bn_stats_part(const float* __restrict__ Hb)
{
    int col = blockIdx.x * 32 + threadIdx.x;
    int r0 = blockIdx.y * (BQ / 16);
    float s = 0.f, ss = 0.f;
    for (int r = threadIdx.y; r < BQ / 16; r += 8) {
        float v = Hb[(size_t)(r0 + r) * HD + col];
        s += v; ss += v * v;
    }
    __shared__ float sh[8][32], sh2[8][32];
    sh[threadIdx.y][threadIdx.x] = s;
    sh2[threadIdx.y][threadIdx.x] = ss;
    __syncthreads();
    if (threadIdx.y == 0) {
        float ts = 0.f, tss = 0.f;
#pragma unroll
        for (int y = 0; y < 8; y++) { ts += sh[y][threadIdx.x]; tss += sh2[y][threadIdx.x]; }
        g_ps[blockIdx.y * HD + col] = ts;
        g_pss[blockIdx.y * HD + col] = tss;
    }
}

__global__ void bn_final(const float* __restrict__ g, const float* __restrict__ be)
{
    int c = blockIdx.x * 256 + threadIdx.x;
    if (c < HD) {
        float s = 0.f, ss = 0.f;
#pragma unroll
        for (int p = 0; p < 16; p++) { s += g_ps[p * HD + c]; ss += g_pss[p * HD + c]; }
        float mu = s / (float)BQ;
        float var = ss / (float)BQ - mu * mu;
        float sc = g[c] * rsqrtf(var + 1e-5f);
        g_scale[c] = sc;
        g_shift[c] = be[c] - mu * sc;
    }
}

template <int WB>
__global__ void bn_relu()
{
    size_t i = ((size_t)blockIdx.x * 256 + threadIdx.x) * 4;
    float4 v = *reinterpret_cast<float4*>(&g_h[i]);
    int c = (int)(i & (HD - 1));
    v.x = fmaxf(v.x * g_scale[c + 0] + g_shift[c + 0], 0.f);
    v.y = fmaxf(v.y * g_scale[c + 1] + g_shift[c + 1], 0.f);
    v.z = fmaxf(v.z * g_scale[c + 2] + g_shift[c + 2], 0.f);
    v.w = fmaxf(v.w * g_scale[c + 3] + g_shift[c + 3], 0.f);
    if (WB) {
        __nv_bfloat162 p0, p1;
        p0.x = __float2bfloat16_rn(v.x); p0.y = __float2bfloat16_rn(v.y);
        p1.x = __float2bfloat16_rn(v.z); p1.y = __float2bfloat16_rn(v.w);
        *reinterpret_cast<__nv_bfloat162*>(&g_hb[i]) = p0;
        *reinterpret_cast<__nv_bfloat162*>(&g_hb[i + 2]) = p1;
    } else {
        *reinterpret_cast<float4*>(&g_h[i]) = v;
    }
}

__global__ void cvt_w2(const float* __restrict__ w)
{
    int i = blockIdx.x * 256 + threadIdx.x;
    if (i < HD * DIN) g_w2b[i] = __float2bfloat16_rn(w[i]);
}

// ================= KL rows =================
__global__ __launch_bounds__(256)
void kl_rows(const float* __restrict__ Z, const float* __restrict__ Q,
             const float* __restrict__ h, const float* __restrict__ W,
             float* __restrict__ orow, int useQ)
{
    __shared__ unsigned long long zp[8][LD];
    __shared__ float wpart[16][8];
    const int tid = threadIdx.x;
    const int lane = tid & 31;
    const int w = tid >> 5;
    const int j = tid;
    const int r0 = blockIdx.x * 16;

    for (int idx = tid; idx < 8 * LD; idx += 256) {
        int rp = idx >> 8, i = idx & 255;
        float za = Z[(size_t)(r0 + 2 * rp) * LD + i];
        float zb = Z[(size_t)(r0 + 2 * rp + 1) * LD + i];
        unsigned long long pk;
        asm("mov.b64 %0, {%1,%2};" : "=l"(pk) : "f"(za), "f"(zb));
        zp[rp][i] = pk;
    }
    __syncthreads();

    unsigned long long acc[8];
#pragma unroll
    for (int rp = 0; rp < 8; rp++) acc[rp] = 0ULL;
    for (int i = 0; i < LD; i++) {
        float wv = W[i * LD + j];
        unsigned long long ww;
        asm("mov.b64 %0, {%1,%1};" : "=l"(ww) : "f"(wv));
#pragma unroll
        for (int rp = 0; rp < 8; rp++)
            asm("fma.rn.f32x2 %0, %1, %2, %0;" : "+l"(acc[rp]) : "l"(zp[rp][i]), "l"(ww));
    }

    float hj = h[j];
#pragma unroll
    for (int rp = 0; rp < 8; rp++) {
        float aA, aB, zA, zB;
        asm("mov.b64 {%0,%1}, %2;" : "=f"(aA), "=f"(aB) : "l"(acc[rp]));
        asm("mov.b64 {%0,%1}, %2;" : "=f"(zA), "=f"(zB) : "l"(zp[rp][j]));
#pragma unroll
        for (int half = 0; half < 2; half++) {
            int r = 2 * rp + half;
            float zj = half ? zB : zA;
            float av = half ? aB : aA;
            float val = zj * (hj + av);
            if (useQ) {
                float qv = Q[(size_t)(r0 + r) * LD + j];
                qv = fminf(fmaxf(qv, 1e-7f), 1.0f - 1e-7f);
                val += (zj > 0.5f) ? __logf(qv) : __logf(1.0f - qv);
            }
#pragma unroll
            for (int s = 16; s > 0; s >>= 1)
                val += __shfl_down_sync(0xffffffffu, val, s);
            if (lane == 0) wpart[r][w] = val;
        }
    }
    __syncthreads();
    if (tid < 16) {
        float s = 0.f;
#pragma unroll
        for (int k = 0; k < 8; k++) s += wpart[tid][k];
        orow[r0 + tid] = s;
    }
}

__global__ void finalize_k(float* __restrict__ out)
{
    __shared__ float red[256];
    int t = threadIdx.x;
    float res[3];
    const float* srcs[3] = {g_part, g_rowpos, g_rowneg};
    int cnts[3] = {4096, BQ, BQ};
#pragma unroll
    for (int p = 0; p < 3; p++) {
        float s = 0.f;
        for (int i = t; i < cnts[p]; i += 256) s += srcs[p][i];
        red[t] = s;
        __syncthreads();
#pragma unroll
        for (int k = 128; k > 0; k >>= 1) {
            if (t < k) red[t] += red[t + k];
            __syncthreads();
        }
        res[p] = red[0];
        __syncthreads();
    }
    if (t == 0) {
        float recon = res[0] / (float)BQ;
        float kl = res[1] / (float)BQ + res[2] / (float)BQ;
        out[0] = -recon - 0.001f * kl;
        out[1] = recon;
        out[2] = kl;
    }
}

extern "C" void kernel_launch(void* const* d_in, const int* in_sizes, int n_in,
                              void* d_out, int out_size)
{
    const float* x      = (const float*)d_in[0];
    const float* rho    = (const float*)d_in[1];
    const float* z_init = (const float*)d_in[2];
    const float* grnd   = (const float*)d_in[3];
    const float* eW1    = (const float*)d_in[4];
    const float* eb1    = (const float*)d_in[5];
    const float* eg1    = (const float*)d_in[6];
    const float* ebe1   = (const float*)d_in[7];
    const float* eW2    = (const float*)d_in[8];
    const float* eb2    = (const float*)d_in[9];
    const float* dW1    = (const float*)d_in[10];
    const float* db1    = (const float*)d_in[11];
    const float* dg1    = (const float*)d_in[12];
    const float* dbe1   = (const float*)d_in[13];
    const float* dW2    = (const float*)d_in[14];
    const float* db2    = (const float*)d_in[15];
    const float* rbm_h  = (const float*)d_in[16];
    const float* rbm_W  = (const float*)d_in[17];

    float* out = (float*)d_out;
    float* out_z = out + 3;
    float* out_zeta = out + 3 + (size_t)BQ * LD;

    float *p_h, *p_q, *p_zeta, *p_zb, *p_rp, *p_rn, *p_part;
    __nv_bfloat16 *p_hb, *p_w2b;
    cudaGetSymbolAddress((void**)&p_h, g_h);
    cudaGetSymbolAddress((void**)&p_hb, g_hb);
    cudaGetSymbolAddress((void**)&p_w2b, g_w2b);
    cudaGetSymbolAddress((void**)&p_q, g_q);
    cudaGetSymbolAddress((void**)&p_zeta, g_zeta);
    cudaGetSymbolAddress((void**)&p_zb, g_zb);
    cudaGetSymbolAddress((void**)&p_rp, g_rowpos);
    cudaGetSymbolAddress((void**)&p_rn, g_rowneg);
    cudaGetSymbolAddress((void**)&p_part, g_part);

    int gibbs_smem = (256 * WP + GR * ZP) * 2 + 256 * 4;
    cudaFuncSetAttribute(gibbs_fused, cudaFuncAttributeMaxDynamicSharedMemorySize, gibbs_smem);
    cudaFuncSetAttribute(gemm_v2<0>, cudaFuncAttributeMaxDynamicSharedMemorySize, V2_SMEM);
    cudaFuncSetAttribute(gemm_v2<1>, cudaFuncAttributeMaxDynamicSharedMemorySize, V2_SMEM);

    // serial; launch #4 = gibbs_fused (verify the L1-reduction prediction)
    cvt_w2<<<(HD * DIN + 255) / 256, 256>>>(dW2);                                        // 1
    gemm_v2<0><<<dim3(2, 128), 256, V2_SMEM>>>(x, DIN, eW1, HD, eb1, p_h, HD, DIN,
                                               nullptr, nullptr, nullptr, nullptr);      // 2  G1
    bn_stats_part<<<dim3(16, 16), dim3(32, 8)>>>(p_h);                                   // 3
    gibbs_fused<<<BQ / GR, 256, gibbs_smem>>>(z_init, grnd, rbm_h, rbm_W, p_zb);         // 4  <- ncu
    bn_final<<<2, 256>>>(eg1, ebe1);                                                     // 5
    bn_relu<0><<<8192, 256>>>();                                                         // 6
    gemm_v2<1><<<dim3(1, 128), 256, V2_SMEM>>>(p_h, HD, eW2, LD, eb2, p_q, LD, HD,
                                               rho, p_zeta, out_z, out_zeta);            // 7  G2
    kl_rows<<<1024, 256>>>(out_z, p_q, rbm_h, rbm_W, p_rp, 1);                           // 8
    kl_rows<<<1024, 256>>>(p_zb, nullptr, rbm_h, rbm_W, p_rn, 0);                        // 9
    gemm_v2<0><<<dim3(2, 128), 256, V2_SMEM>>>(p_zeta, LD, dW1, HD, db1, p_h, HD, LD,
                                               nullptr, nullptr, nullptr, nullptr);      // 10 G3
    bn_stats_part<<<dim3(16, 16), dim3(32, 8)>>>(p_h);                                   // 11
    bn_final<<<2, 256>>>(dg1, dbe1);                                                     // 12
    bn_relu<1><<<8192, 256>>>();                                                         // 13
    gemm4_loss<<<dim3(32, 128), 256>>>(p_hb, p_w2b, db2, x, p_part);                     // 14
    finalize_k<<<1, 256>>>(out);                                                         // 15
}